// round 9
// baseline (speedup 1.0000x reference)
#include <cuda_runtime.h>
#include <math.h>

// Problem constants
#define BB   64
#define STT  512
#define SLL  64
#define DD   256
#define HH   256
#define G4   1024
#define NCL  20
#define EPSV 1e-8f
#define NBLK 128

typedef unsigned long long ull;

// ---------------- scratch (static device globals; no allocation) ----------------
__device__ __align__(1024) float g_xw_pf[BB*STT*G4];
__device__ __align__(1024) float g_xw_pb[BB*STT*G4];
__device__ __align__(1024) float g_xw_hf[BB*SLL*G4];
__device__ __align__(1024) float g_xw_hb[BB*SLL*G4];
__device__ __align__(1024) float g_cpf[BB*STT*HH];
__device__ __align__(1024) float g_cpb[BB*STT*HH];
__device__ __align__(1024) float g_chf[BB*SLL*HH];
__device__ __align__(1024) float g_chb[BB*SLL*HH];
__device__ __align__(1024) float g_mvp[BB*STT*2];
__device__ __align__(1024) float g_mvh[BB*SLL*2];
__device__ __align__(1024) float g_hping[2*2*2*BB*HH]; // [seq][dir][parity][B*H]
__device__ __align__(1024) float g_fin[4*BB*HH];       // pT_f, pT_b, hT_f, hT_b
__device__ volatile unsigned g_gen;
__device__ unsigned g_count;

// ---------------- packed f32x2 helpers ----------------
__device__ __forceinline__ ull fma2(ull a, ull b, ull c) {
    ull d; asm("fma.rn.f32x2 %0, %1, %2, %3;" : "=l"(d) : "l"(a), "l"(b), "l"(c)); return d;
}
__device__ __forceinline__ ull add2(ull a, ull b) {
    ull d; asm("add.rn.f32x2 %0, %1, %2;" : "=l"(d) : "l"(a), "l"(b)); return d;
}
__device__ __forceinline__ float lo2(ull v) { return __uint_as_float((unsigned)v); }
__device__ __forceinline__ float hi2(ull v) { return __uint_as_float((unsigned)(v >> 32)); }

__device__ __forceinline__ void ldcg_u64x2(const void* p, ull &a, ull &b) {
    asm volatile("ld.global.cg.v2.u64 {%0,%1}, [%2];" : "=l"(a), "=l"(b) : "l"(p));
}
__device__ __forceinline__ void ldg_u64x2(const void* p, ull &a, ull &b) {
    asm("ld.global.nc.v2.u64 {%0,%1}, [%2];" : "=l"(a), "=l"(b) : "l"(p));
}
__device__ __forceinline__ float ldcg_f(const float* p) {
    float v; asm volatile("ld.global.cg.f32 %0, [%1];" : "=f"(v) : "l"(p)); return v;
}
__device__ __forceinline__ ull shflx64(ull v, int m) {
    return __shfl_xor_sync(0xffffffffu, v, m);
}

// Fast-but-accurate activations: ex2.approx (~2^-22 rel) + rcp.approx
__device__ __forceinline__ float sigf(float x) {
    return __fdividef(1.f, 1.f + __expf(-x));
}
__device__ __forceinline__ float tanhp(float x) {
    return __fdividef(2.f, 1.f + __expf(-2.f * x)) - 1.f;
}

// ---------------- software grid barrier (self-resetting, replay-safe) ----------------
__device__ __forceinline__ void grid_barrier(unsigned &lgen) {
    __syncthreads();
    if (threadIdx.x == 0) {
        __threadfence();
        unsigned prev = atomicAdd(&g_count, 1u);
        if (prev == gridDim.x - 1u) {
            g_count = 0u;
            __threadfence();
            g_gen = lgen + 1u;
        } else {
            if (g_gen == lgen) {
                __nanosleep(64);
                while (g_gen == lgen) { __nanosleep(128); }
            }
        }
        __threadfence();
    }
    lgen += 1u;
    __syncthreads();
}

// ---------------- scatter-reduce over kp (8 lanes); valid lane: b4 == (kp&3), pass == kp>>2
__device__ __forceinline__ void kreduce4(ull acc[4][4], int kp, float out[4]) {
#pragma unroll
    for (int g = 0; g < 4; g++) {
        ull t1[2];
#pragma unroll
        for (int i = 0; i < 2; i++) {
            ull keep = (kp & 1) ? acc[g][2*i+1] : acc[g][2*i];
            ull send = (kp & 1) ? acc[g][2*i]   : acc[g][2*i+1];
            t1[i] = add2(keep, shflx64(send, 4));
        }
        ull keep = (kp & 2) ? t1[1] : t1[0];
        ull send = (kp & 2) ? t1[0] : t1[1];
        ull t2 = add2(keep, shflx64(send, 8));
        ull t3 = add2(t2, shflx64(t2, 16));
        out[g] = lo2(t3) + hi2(t3);
    }
}

// gate pre-activations for this lane's batch b = bt*8+kp, 4 gates, via 2-pass MMA
__device__ __forceinline__ void gate_mma(const float* __restrict__ hbase, size_t bstride,
                                         const ull w[4][8][2], int bt, int kp, float pre[4])
{
#pragma unroll
    for (int pass = 0; pass < 2; pass++) {
        ull acc[4][4];
#pragma unroll
        for (int g = 0; g < 4; g++)
#pragma unroll
            for (int b4 = 0; b4 < 4; b4++) acc[g][b4] = 0ull;
#pragma unroll
        for (int b4 = 0; b4 < 4; b4++) {
            const float* hp = hbase + (size_t)(bt*8 + pass*4 + b4) * bstride;
#pragma unroll
            for (int j = 0; j < 8; j++) {
                ull hx, hy;
                ldcg_u64x2(hp + (kp + j*8) * 4, hx, hy);
#pragma unroll
                for (int g = 0; g < 4; g++) {
                    acc[g][b4] = fma2(hx, w[g][j][0], acc[g][b4]);
                    acc[g][b4] = fma2(hy, w[g][j][1], acc[g][b4]);
                }
            }
        }
        float r[4];
        kreduce4(acc, kp, r);
        if ((kp >> 2) == pass) { pre[0]=r[0]; pre[1]=r[1]; pre[2]=r[2]; pre[3]=r[3]; }
    }
}

__device__ __forceinline__ float lstm_cell(const float pre[4], const float xv[4], float &c) {
    float gi = sigf(pre[0] + xv[0]);
    float gf = sigf(pre[1] + xv[1]);
    float gg = tanhp(pre[2] + xv[2]);
    float go = sigf(pre[3] + xv[3]);
    c = gf * c + gi * gg;
    return go * tanhp(c);
}

// ---------------- streaming GEMM, register weights + FFMA2; text+label in one launch ----
__global__ void __launch_bounds__(256, 1) gemm2(
    const int* __restrict__ tokP, const int* __restrict__ tokH,
    const float* __restrict__ emb,
    const float* __restrict__ Wf, const float* __restrict__ Wb,
    const float* __restrict__ bihf, const float* __restrict__ bhhf,
    const float* __restrict__ bihb, const float* __restrict__ bhhb,
    float* __restrict__ outPF, float* __restrict__ outPB,
    float* __restrict__ outHF, float* __restrict__ outHB)
{
    const int MP = BB * STT;
    const int MT = BB * (STT + SLL);
    int tid = threadIdx.x;
    int bt = tid >> 5, lane = tid & 31;
    int ul = lane & 3, kp = lane >> 2;
    int dir = blockIdx.y;
    int n0 = blockIdx.x * 16;
    const float* W   = dir ? Wb : Wf;
    const float* bih = dir ? bihb : bihf;
    const float* bhh = dir ? bhhb : bhhf;

    ull w[4][8][2];
    float bias[4];
#pragma unroll
    for (int q = 0; q < 4; q++) {
        int r = n0 + ul*4 + q;
        bias[q] = __ldg(bih + r) + __ldg(bhh + r);
#pragma unroll
        for (int j = 0; j < 8; j++)
            ldg_u64x2(W + (size_t)r * DD + (kp + j*8) * 4, w[q][j][0], w[q][j][1]);
    }

    for (int m0 = 0; m0 < MT; m0 += 64) {
        const int* tok = (m0 < MP) ? tokP : tokH;
        int mo = (m0 < MP) ? m0 : (m0 - MP);
        float* out;
        if (m0 < MP) out = dir ? outPB : outPF;
        else         out = dir ? outHB : outHF;

        int tkr = 0;
        if (lane < 8) tkr = __ldg(tok + mo + bt*8 + lane);
        float s[4];
#pragma unroll
        for (int pass = 0; pass < 2; pass++) {
            ull acc[4][4];
#pragma unroll
            for (int q = 0; q < 4; q++)
#pragma unroll
                for (int b4 = 0; b4 < 4; b4++) acc[q][b4] = 0ull;
#pragma unroll
            for (int b4 = 0; b4 < 4; b4++) {
                int tk = __shfl_sync(0xffffffffu, tkr, pass*4 + b4);
                const float* base = emb + (size_t)tk * DD;
#pragma unroll
                for (int j = 0; j < 8; j++) {
                    ull hx, hy;
                    ldg_u64x2(base + (kp + j*8) * 4, hx, hy);
#pragma unroll
                    for (int q = 0; q < 4; q++) {
                        acc[q][b4] = fma2(hx, w[q][j][0], acc[q][b4]);
                        acc[q][b4] = fma2(hy, w[q][j][1], acc[q][b4]);
                    }
                }
            }
            float r[4];
            kreduce4(acc, kp, r);
            if ((kp >> 2) == pass) { s[0]=r[0]; s[1]=r[1]; s[2]=r[2]; s[3]=r[3]; }
        }
        int m = mo + bt*8 + kp;
        float4 o4 = make_float4(s[0]+bias[0], s[1]+bias[1], s[2]+bias[2], s[3]+bias[3]);
        *(float4*)(out + (size_t)m * G4 + n0 + ul*4) = o4;
    }
}

// ---------------- context BiLSTM recurrence: premise + hypothesis fused, persistent ----
// 128 blocks: dir = blockIdx.x>>6 (0 fwd, 1 bwd); 4 hidden units per block.
__global__ void __launch_bounds__(256, 1) lstm_ctx(
    const float* __restrict__ xwPF, const float* __restrict__ xwPB,
    const float* __restrict__ xwHF, const float* __restrict__ xwHB,
    const float* __restrict__ WhhF, const float* __restrict__ WhhB,
    float* __restrict__ hsPF, float* __restrict__ hsPB,
    float* __restrict__ hsHF, float* __restrict__ hsHB)
{
    int tid = threadIdx.x;
    int bt = tid >> 5, lane = tid & 31;
    int ul = lane & 3, kp = lane >> 2;
    int dir = blockIdx.x >> 6;
    int bd  = blockIdx.x & 63;
    int u   = bd * 4 + ul;
    const float* xwP = dir ? xwPB : xwPF;
    const float* xwH = dir ? xwHB : xwHF;
    const float* Whh = dir ? WhhB : WhhF;
    float* hsP = dir ? hsPB : hsPF;
    float* hsH = dir ? hsHB : hsHF;
    int b = bt*8 + kp;

    ull w[4][8][2];
#pragma unroll
    for (int g = 0; g < 4; g++)
#pragma unroll
        for (int j = 0; j < 8; j++)
            ldg_u64x2(Whh + (size_t)(g*HH + u) * HH + (kp + j*8) * 4, w[g][j][0], w[g][j][1]);

    float cP = 0.f, cH = 0.f;
    unsigned lgen = g_gen;
    __syncthreads();

    for (int s = 0; s < STT; s++) {
        int ttP = dir ? (STT - 1 - s) : s;
        // prefetch x-projections (independent of h): hide DRAM latency behind barrier
        float xvP[4];
#pragma unroll
        for (int g = 0; g < 4; g++)
            xvP[g] = __ldg(xwP + ((size_t)b * STT + ttP) * G4 + g*HH + u);
        int ttH = dir ? (SLL - 1 - s) : s;
        float xvH[4];
        if (s < SLL) {
#pragma unroll
            for (int g = 0; g < 4; g++)
                xvH[g] = __ldg(xwH + ((size_t)b * SLL + ttH) * G4 + g*HH + u);
        }

        if (s > 0) grid_barrier(lgen);

        float preP[4] = {0.f, 0.f, 0.f, 0.f};
        if (s > 0) {
            int tp = dir ? (ttP + 1) : (ttP - 1);
            gate_mma(hsP + (size_t)tp * HH, (size_t)STT * HH, w, bt, kp, preP);
        }
        float hP = lstm_cell(preP, xvP, cP);
        hsP[((size_t)b * STT + ttP) * HH + u] = hP;

        if (s < SLL) {
            float preH[4] = {0.f, 0.f, 0.f, 0.f};
            if (s > 0) {
                int tp = dir ? (ttH + 1) : (ttH - 1);
                gate_mma(hsH + (size_t)tp * HH, (size_t)SLL * HH, w, bt, kp, preH);
            }
            float hH = lstm_cell(preH, xvH, cH);
            hsH[((size_t)b * SLL + ttH) * HH + u] = hH;
        }
    }
}

// ---------------- aggregation BiLSTM: premise + hypothesis fused, finals only ----------
__global__ void __launch_bounds__(256, 1) lstm_agg(
    const float* __restrict__ mvP, const float* __restrict__ mvH,
    const float* __restrict__ WihF, const float* __restrict__ WihB,
    const float* __restrict__ bihF, const float* __restrict__ bhhF,
    const float* __restrict__ bihB, const float* __restrict__ bhhB,
    const float* __restrict__ WhhF, const float* __restrict__ WhhB,
    float* __restrict__ hping, float* __restrict__ fin)
{
    int tid = threadIdx.x;
    int bt = tid >> 5, lane = tid & 31;
    int ul = lane & 3, kp = lane >> 2;
    int dir = blockIdx.x >> 6;
    int bd  = blockIdx.x & 63;
    int u   = bd * 4 + ul;
    const float* Wih = dir ? WihB : WihF;
    const float* Whh = dir ? WhhB : WhhF;
    const float* bih = dir ? bihB : bihF;
    const float* bhh = dir ? bhhB : bhhF;
    float* finP = fin + (size_t)(0*2 + dir) * (BB*HH);
    float* finH = fin + (size_t)(1*2 + dir) * (BB*HH);
    float* bufP0 = hping + (size_t)((0*2 + dir)*2 + 0) * (BB*HH);
    float* bufP1 = hping + (size_t)((0*2 + dir)*2 + 1) * (BB*HH);
    float* bufH0 = hping + (size_t)((1*2 + dir)*2 + 0) * (BB*HH);
    float* bufH1 = hping + (size_t)((1*2 + dir)*2 + 1) * (BB*HH);
    int b = bt*8 + kp;

    ull w[4][8][2];
    float wih0[4], wih1[4], bias[4];
#pragma unroll
    for (int g = 0; g < 4; g++) {
        int r = g*HH + u;
#pragma unroll
        for (int j = 0; j < 8; j++)
            ldg_u64x2(Whh + (size_t)r * HH + (kp + j*8) * 4, w[g][j][0], w[g][j][1]);
        wih0[g] = __ldg(Wih + r*2);
        wih1[g] = __ldg(Wih + r*2 + 1);
        bias[g] = __ldg(bih + r) + __ldg(bhh + r);
    }

    float cP = 0.f, cH = 0.f;
    unsigned lgen = g_gen;
    __syncthreads();

    for (int s = 0; s < STT; s++) {
        int ttP = dir ? (STT - 1 - s) : s;
        float2 mvvP;
        mvvP.x = ldcg_f(mvP + ((size_t)b * STT + ttP) * 2);
        mvvP.y = ldcg_f(mvP + ((size_t)b * STT + ttP) * 2 + 1);
        float xvP[4];
#pragma unroll
        for (int g = 0; g < 4; g++)
            xvP[g] = mvvP.x * wih0[g] + mvvP.y * wih1[g] + bias[g];
        int ttH = dir ? (SLL - 1 - s) : s;
        float xvH[4];
        if (s < SLL) {
            float2 mvvH;
            mvvH.x = ldcg_f(mvH + ((size_t)b * SLL + ttH) * 2);
            mvvH.y = ldcg_f(mvH + ((size_t)b * SLL + ttH) * 2 + 1);
#pragma unroll
            for (int g = 0; g < 4; g++)
                xvH[g] = mvvH.x * wih0[g] + mvvH.y * wih1[g] + bias[g];
        }

        if (s > 0) grid_barrier(lgen);

        {
            float* cur        = (s & 1) ? bufP1 : bufP0;
            const float* prev = (s & 1) ? bufP0 : bufP1;
            float pre[4] = {0.f, 0.f, 0.f, 0.f};
            if (s > 0) gate_mma(prev, (size_t)HH, w, bt, kp, pre);
            float h = lstm_cell(pre, xvP, cP);
            cur[(size_t)b * HH + u] = h;
            if (s == STT - 1) finP[(size_t)b * HH + u] = h;
        }
        if (s < SLL) {
            float* cur        = (s & 1) ? bufH1 : bufH0;
            const float* prev = (s & 1) ? bufH0 : bufH1;
            float pre[4] = {0.f, 0.f, 0.f, 0.f};
            if (s > 0) gate_mma(prev, (size_t)HH, w, bt, kp, pre);
            float h = lstm_cell(pre, xvH, cH);
            cur[(size_t)b * HH + u] = h;
            if (s == SLL - 1) finH[(size_t)b * HH + u] = h;
        }
    }
}

// ---------------- multi-perspective cosine matching (both sequences, one launch) --------
__global__ void __launch_bounds__(256) match_kernel(
    const float* __restrict__ cpf, const float* __restrict__ cpb,
    const float* __restrict__ chf, const float* __restrict__ chb,
    const float* __restrict__ w1, const float* __restrict__ w2,
    float* __restrict__ mvp, float* __restrict__ mvh)
{
    int warp = (blockIdx.x * blockDim.x + threadIdx.x) >> 5;
    int lane = threadIdx.x & 31;
    const float *x1, *y1v, *x2, *y2v;
    float* mv;
    int S;
    int b, s;
    if (warp < BB * STT) {
        b = warp / STT; s = warp % STT; S = STT;
        x1  = cpf + ((size_t)b * STT + s) * HH;
        y1v = chf + ((size_t)b * SLL + (SLL - 1)) * HH;
        x2  = cpb + ((size_t)b * STT + s) * HH;
        y2v = chb + ((size_t)b * SLL) * HH;
        mv  = mvp;
    } else {
        int wq = warp - BB * STT;
        b = wq / SLL; s = wq % SLL; S = SLL;
        x1  = chf + ((size_t)b * SLL + s) * HH;
        y1v = cpf + ((size_t)b * STT + (STT - 1)) * HH;
        x2  = chb + ((size_t)b * SLL + s) * HH;
        y2v = cpb + ((size_t)b * STT) * HH;
        mv  = mvh;
    }
    float n1 = 0.f, dx1 = 0.f, dy1 = 0.f, n2 = 0.f, dx2 = 0.f, dy2 = 0.f;
    for (int k = lane; k < HH; k += 32) {
        float wv = __ldg(w1 + k); float ww = wv * wv;
        float xv = ldcg_f(x1 + k), yv = ldcg_f(y1v + k);
        n1 += ww * xv * yv; dx1 += ww * xv * xv; dy1 += ww * yv * yv;
        float wv2 = __ldg(w2 + k); float ww2 = wv2 * wv2;
        float xv2 = ldcg_f(x2 + k), yv2 = ldcg_f(y2v + k);
        n2 += ww2 * xv2 * yv2; dx2 += ww2 * xv2 * xv2; dy2 += ww2 * yv2 * yv2;
    }
#pragma unroll
    for (int o = 16; o; o >>= 1) {
        n1 += __shfl_xor_sync(0xffffffffu, n1, o);
        dx1 += __shfl_xor_sync(0xffffffffu, dx1, o);
        dy1 += __shfl_xor_sync(0xffffffffu, dy1, o);
        n2 += __shfl_xor_sync(0xffffffffu, n2, o);
        dx2 += __shfl_xor_sync(0xffffffffu, dx2, o);
        dy2 += __shfl_xor_sync(0xffffffffu, dy2, o);
    }
    if (lane == 0) {
        mv[((size_t)b * S + s) * 2]     = n1 / fmaxf(sqrtf(dx1) * sqrtf(dy1), EPSV);
        mv[((size_t)b * S + s) * 2 + 1] = n2 / fmaxf(sqrtf(dx2) * sqrtf(dy2), EPSV);
    }
}

// ---------------- final MLP ----------------
__global__ void __launch_bounds__(256) final_fc(
    const float* __restrict__ fin,
    const float* __restrict__ W1, const float* __restrict__ b1,
    const float* __restrict__ W2, const float* __restrict__ b2,
    float* __restrict__ out)
{
    __shared__ float xs[1024];
    __shared__ float y1[512];
    int b = blockIdx.x, t = threadIdx.x;
    // fin segments: [pT_f][pT_b][hT_f][hT_b], each BB*HH
    xs[t]       = ldcg_f(fin + (size_t)(0*BB + b) * HH + t);
    xs[256 + t] = ldcg_f(fin + (size_t)(1*BB + b) * HH + t);
    xs[512 + t] = ldcg_f(fin + (size_t)(2*BB + b) * HH + t);
    xs[768 + t] = ldcg_f(fin + (size_t)(3*BB + b) * HH + t);
    __syncthreads();
    int w = t >> 5, lane = t & 31;
    for (int j0 = w * 4; j0 < 512; j0 += 32) {
#pragma unroll
        for (int jj = 0; jj < 4; jj++) {
            int jo = j0 + jj;
            const float4* wr = (const float4*)(W1 + (size_t)jo * 1024);
            float acc = 0.f;
            for (int i = lane; i < 256; i += 32) {
                float4 wv = __ldg(wr + i);
                float4 xv = *(const float4*)(xs + i*4);
                acc += wv.x*xv.x + wv.y*xv.y + wv.z*xv.z + wv.w*xv.w;
            }
#pragma unroll
            for (int o = 16; o; o >>= 1) acc += __shfl_xor_sync(0xffffffffu, acc, o);
            if (lane == 0) y1[jo] = tanhf(acc + __ldg(b1 + jo));
        }
    }
    __syncthreads();
    for (int jo = w; jo < NCL; jo += 8) {
        const float4* wr = (const float4*)(W2 + (size_t)jo * 512);
        float acc = 0.f;
        for (int i = lane; i < 128; i += 32) {
            float4 wv = __ldg(wr + i);
            float4 xv = *(const float4*)(y1 + i*4);
            acc += wv.x*xv.x + wv.y*xv.y + wv.z*xv.z + wv.w*xv.w;
        }
#pragma unroll
        for (int o = 16; o; o >>= 1) acc += __shfl_xor_sync(0xffffffffu, acc, o);
        if (lane == 0) out[(size_t)b*NCL + jo] = acc + __ldg(b2 + jo);
    }
}

// ---------------- host ----------------
extern "C" void kernel_launch(void* const* d_in, const int* in_sizes, int n_in,
                              void* d_out, int out_size)
{
    const int*   text  = (const int*)d_in[0];
    const int*   label = (const int*)d_in[1];
    const float* emb   = (const float*)d_in[2];
    const float* cWihF = (const float*)d_in[3];
    const float* cWhhF = (const float*)d_in[4];
    const float* cbihF = (const float*)d_in[5];
    const float* cbhhF = (const float*)d_in[6];
    const float* cWihB = (const float*)d_in[7];
    const float* cWhhB = (const float*)d_in[8];
    const float* cbihB = (const float*)d_in[9];
    const float* cbhhB = (const float*)d_in[10];
    const float* w1    = (const float*)d_in[11];
    const float* w2    = (const float*)d_in[12];
    const float* aWihF = (const float*)d_in[13];
    const float* aWhhF = (const float*)d_in[14];
    const float* abihF = (const float*)d_in[15];
    const float* abhhF = (const float*)d_in[16];
    const float* aWihB = (const float*)d_in[17];
    const float* aWhhB = (const float*)d_in[18];
    const float* abihB = (const float*)d_in[19];
    const float* abhhB = (const float*)d_in[20];
    const float* fc1W  = (const float*)d_in[21];
    const float* fc1b  = (const float*)d_in[22];
    const float* fc2W  = (const float*)d_in[23];
    const float* fc2b  = (const float*)d_in[24];
    float* out = (float*)d_out;

    void* p;
    cudaGetSymbolAddress(&p, g_xw_pf); float* xwpf = (float*)p;
    cudaGetSymbolAddress(&p, g_xw_pb); float* xwpb = (float*)p;
    cudaGetSymbolAddress(&p, g_xw_hf); float* xwhf = (float*)p;
    cudaGetSymbolAddress(&p, g_xw_hb); float* xwhb = (float*)p;
    cudaGetSymbolAddress(&p, g_cpf);   float* cpf  = (float*)p;
    cudaGetSymbolAddress(&p, g_cpb);   float* cpb  = (float*)p;
    cudaGetSymbolAddress(&p, g_chf);   float* chf  = (float*)p;
    cudaGetSymbolAddress(&p, g_chb);   float* chb  = (float*)p;
    cudaGetSymbolAddress(&p, g_mvp);   float* mvp  = (float*)p;
    cudaGetSymbolAddress(&p, g_mvh);   float* mvh  = (float*)p;
    cudaGetSymbolAddress(&p, g_hping); float* hping = (float*)p;
    cudaGetSymbolAddress(&p, g_fin);   float* fin  = (float*)p;

    // Force 1 CTA/SM on the persistent kernels: all 128 blocks co-resident, one SM each.
    const int DUMMY_SMEM = 120 * 1024;
    cudaFuncSetAttribute(lstm_ctx, cudaFuncAttributeMaxDynamicSharedMemorySize, DUMMY_SMEM);
    cudaFuncSetAttribute(lstm_agg, cudaFuncAttributeMaxDynamicSharedMemorySize, DUMMY_SMEM);

    // 1) xW precompute for both sequences and both directions (one launch)
    gemm2<<<dim3(64, 2), 256>>>(text, label, emb, cWihF, cWihB,
                                cbihF, cbhhF, cbihB, cbhhB,
                                xwpf, xwpb, xwhf, xwhb);

    // 2) context BiLSTM recurrence, premise + hypothesis fused (persistent)
    lstm_ctx<<<NBLK, 256, DUMMY_SMEM>>>(xwpf, xwpb, xwhf, xwhb,
                                        cWhhF, cWhhB, cpf, cpb, chf, chb);

    // 3) multi-perspective matching (both sequences)
    match_kernel<<<(BB*STT + BB*SLL)/8, 256>>>(cpf, cpb, chf, chb, w1, w2, mvp, mvh);

    // 4) aggregation BiLSTM, premise + hypothesis fused (persistent, finals only)
    lstm_agg<<<NBLK, 256, DUMMY_SMEM>>>(mvp, mvh, aWihF, aWihB,
                                        abihF, abhhF, abihB, abhhB,
                                        aWhhF, aWhhB, hping, fin);

    // 5) final MLP
    final_fc<<<BB, 256>>>(fin, fc1W, fc1b, fc2W, fc2b, out);
}

// round 16
// speedup vs baseline: 1.0394x; 1.0394x over previous
#include <cuda_runtime.h>
#include <math.h>

// Problem constants
#define BB   64
#define STT  512
#define SLL  64
#define DD   256
#define HH   256
#define G4   1024
#define NCL  20
#define EPSV 1e-8f
#define NBLK 128

typedef unsigned long long ull;

// ---------------- scratch (static device globals; no allocation) ----------------
__device__ __align__(1024) float g_xw_pf[BB*STT*G4];
__device__ __align__(1024) float g_xw_pb[BB*STT*G4];
__device__ __align__(1024) float g_xw_hf[BB*SLL*G4];
__device__ __align__(1024) float g_xw_hb[BB*SLL*G4];
__device__ __align__(1024) float g_cpf[BB*STT*HH];
__device__ __align__(1024) float g_cpb[BB*STT*HH];
__device__ __align__(1024) float g_chf[BB*SLL*HH];
__device__ __align__(1024) float g_chb[BB*SLL*HH];
__device__ __align__(1024) float g_mvp[BB*STT*2];
__device__ __align__(1024) float g_mvh[BB*SLL*2];
__device__ __align__(1024) float g_hping[2*2*2*BB*HH]; // [seq][dir][parity][B*H]
__device__ __align__(1024) float g_fin[4*BB*HH];       // pT_f, pT_b, hT_f, hT_b
__device__ volatile unsigned g_genA[2];                // per-direction barrier generation
__device__ unsigned g_cntA[2];                         // per-direction arrival count

// ---------------- packed f32x2 helpers ----------------
__device__ __forceinline__ ull fma2(ull a, ull b, ull c) {
    ull d; asm("fma.rn.f32x2 %0, %1, %2, %3;" : "=l"(d) : "l"(a), "l"(b), "l"(c)); return d;
}
__device__ __forceinline__ ull add2(ull a, ull b) {
    ull d; asm("add.rn.f32x2 %0, %1, %2;" : "=l"(d) : "l"(a), "l"(b)); return d;
}
__device__ __forceinline__ float lo2(ull v) { return __uint_as_float((unsigned)v); }
__device__ __forceinline__ float hi2(ull v) { return __uint_as_float((unsigned)(v >> 32)); }

// NON-volatile cg load: schedulable/pipelinable by ptxas. Safety against hoisting
// above the sw barrier comes from the zoff data dependency at the call site.
__device__ __forceinline__ void ldcg2(const void* p, ull &a, ull &b) {
    asm("ld.global.cg.v2.u64 {%0,%1}, [%2];" : "=l"(a), "=l"(b) : "l"(p));
}
__device__ __forceinline__ void ldg_u64x2(const void* p, ull &a, ull &b) {
    asm("ld.global.nc.v2.u64 {%0,%1}, [%2];" : "=l"(a), "=l"(b) : "l"(p));
}
__device__ __forceinline__ ull shflx64(ull v, int m) {
    return __shfl_xor_sync(0xffffffffu, v, m);
}
// Opaque zero derived from the barrier generation: data-dependency fence for loads.
__device__ __forceinline__ unsigned opaque_zero(unsigned v) {
    unsigned z; asm("and.b32 %0, %1, 0;" : "=r"(z) : "r"(v)); return z;
}

// Fast-but-accurate activations: ex2.approx (~2^-22 rel) + rcp.approx
__device__ __forceinline__ float sigf(float x) {
    return __fdividef(1.f, 1.f + __expf(-x));
}
__device__ __forceinline__ float tanhp(float x) {
    return __fdividef(2.f, 1.f + __expf(-2.f * x)) - 1.f;
}

// ---------------- per-domain software grid barrier (self-resetting, replay-safe) -------
__device__ __forceinline__ void grid_barrier(int dom, unsigned fan, unsigned &lgen) {
    __syncthreads();
    if (threadIdx.x == 0) {
        __threadfence();
        unsigned prev = atomicAdd(&g_cntA[dom], 1u);
        if (prev == fan - 1u) {
            g_cntA[dom] = 0u;
            __threadfence();
            g_genA[dom] = lgen + 1u;
        } else {
            if (g_genA[dom] == lgen) {
                while (g_genA[dom] == lgen) { __nanosleep(64); }
            }
        }
        __threadfence();
    }
    lgen += 1u;
    __syncthreads();
}

// ---------------- scatter-reduce over kp (8 lanes); valid lane: b4 == (kp&3), pass == kp>>2
__device__ __forceinline__ void kreduce4(ull acc[4][4], int kp, float out[4]) {
#pragma unroll
    for (int g = 0; g < 4; g++) {
        ull t1[2];
#pragma unroll
        for (int i = 0; i < 2; i++) {
            ull keep = (kp & 1) ? acc[g][2*i+1] : acc[g][2*i];
            ull send = (kp & 1) ? acc[g][2*i]   : acc[g][2*i+1];
            t1[i] = add2(keep, shflx64(send, 4));
        }
        ull keep = (kp & 2) ? t1[1] : t1[0];
        ull send = (kp & 2) ? t1[0] : t1[1];
        ull t2 = add2(keep, shflx64(send, 8));
        ull t3 = add2(t2, shflx64(t2, 16));
        out[g] = lo2(t3) + hi2(t3);
    }
}

// gate pre-activations for this lane's batch b = bt*8+kp, 4 gates, via 2-pass MMA.
// hbase must already carry the zoff barrier token.
__device__ __forceinline__ void gate_mma(const float* __restrict__ hbase, size_t bstride,
                                         const ull w[4][8][2], int bt, int kp, float pre[4])
{
#pragma unroll
    for (int pass = 0; pass < 2; pass++) {
        ull acc[4][4];
#pragma unroll
        for (int g = 0; g < 4; g++)
#pragma unroll
            for (int b4 = 0; b4 < 4; b4++) acc[g][b4] = 0ull;
#pragma unroll
        for (int b4 = 0; b4 < 4; b4++) {
            const float* hp = hbase + (size_t)(bt*8 + pass*4 + b4) * bstride;
#pragma unroll
            for (int j = 0; j < 8; j++) {
                ull hx, hy;
                ldcg2(hp + (kp + j*8) * 4, hx, hy);
#pragma unroll
                for (int g = 0; g < 4; g++) {
                    acc[g][b4] = fma2(hx, w[g][j][0], acc[g][b4]);
                    acc[g][b4] = fma2(hy, w[g][j][1], acc[g][b4]);
                }
            }
        }
        float r[4];
        kreduce4(acc, kp, r);
        if ((kp >> 2) == pass) { pre[0]=r[0]; pre[1]=r[1]; pre[2]=r[2]; pre[3]=r[3]; }
    }
}

__device__ __forceinline__ float lstm_cell(const float pre[4], const float xv[4], float &c) {
    float gi = sigf(pre[0] + xv[0]);
    float gf = sigf(pre[1] + xv[1]);
    float gg = tanhp(pre[2] + xv[2]);
    float go = sigf(pre[3] + xv[3]);
    c = gf * c + gi * gg;
    return go * tanhp(c);
}

// ---------------- streaming GEMM, register weights + FFMA2; text+label in one launch ----
__global__ void __launch_bounds__(256, 1) gemm2(
    const int* __restrict__ tokP, const int* __restrict__ tokH,
    const float* __restrict__ emb,
    const float* __restrict__ Wf, const float* __restrict__ Wb,
    const float* __restrict__ bihf, const float* __restrict__ bhhf,
    const float* __restrict__ bihb, const float* __restrict__ bhhb,
    float* __restrict__ outPF, float* __restrict__ outPB,
    float* __restrict__ outHF, float* __restrict__ outHB)
{
    const int MP = BB * STT;
    const int MT = BB * (STT + SLL);
    int tid = threadIdx.x;
    int bt = tid >> 5, lane = tid & 31;
    int ul = lane & 3, kp = lane >> 2;
    int dir = blockIdx.y;
    int n0 = blockIdx.x * 16;
    const float* W   = dir ? Wb : Wf;
    const float* bih = dir ? bihb : bihf;
    const float* bhh = dir ? bhhb : bhhf;

    ull w[4][8][2];
    float bias[4];
#pragma unroll
    for (int q = 0; q < 4; q++) {
        int r = n0 + ul*4 + q;
        bias[q] = __ldg(bih + r) + __ldg(bhh + r);
#pragma unroll
        for (int j = 0; j < 8; j++)
            ldg_u64x2(W + (size_t)r * DD + (kp + j*8) * 4, w[q][j][0], w[q][j][1]);
    }

    for (int m0 = 0; m0 < MT; m0 += 64) {
        const int* tok = (m0 < MP) ? tokP : tokH;
        int mo = (m0 < MP) ? m0 : (m0 - MP);
        float* out;
        if (m0 < MP) out = dir ? outPB : outPF;
        else         out = dir ? outHB : outHF;

        int tkr = 0;
        if (lane < 8) tkr = __ldg(tok + mo + bt*8 + lane);
        float s[4];
#pragma unroll
        for (int pass = 0; pass < 2; pass++) {
            ull acc[4][4];
#pragma unroll
            for (int q = 0; q < 4; q++)
#pragma unroll
                for (int b4 = 0; b4 < 4; b4++) acc[q][b4] = 0ull;
#pragma unroll
            for (int b4 = 0; b4 < 4; b4++) {
                int tk = __shfl_sync(0xffffffffu, tkr, pass*4 + b4);
                const float* base = emb + (size_t)tk * DD;
#pragma unroll
                for (int j = 0; j < 8; j++) {
                    ull hx, hy;
                    ldg_u64x2(base + (kp + j*8) * 4, hx, hy);
#pragma unroll
                    for (int q = 0; q < 4; q++) {
                        acc[q][b4] = fma2(hx, w[q][j][0], acc[q][b4]);
                        acc[q][b4] = fma2(hy, w[q][j][1], acc[q][b4]);
                    }
                }
            }
            float r[4];
            kreduce4(acc, kp, r);
            if ((kp >> 2) == pass) { s[0]=r[0]; s[1]=r[1]; s[2]=r[2]; s[3]=r[3]; }
        }
        int m = mo + bt*8 + kp;
        float4 o4 = make_float4(s[0]+bias[0], s[1]+bias[1], s[2]+bias[2], s[3]+bias[3]);
        *(float4*)(out + (size_t)m * G4 + n0 + ul*4) = o4;
    }
}

// ---------------- context BiLSTM recurrence: premise + hypothesis fused, persistent ----
// 128 blocks: dir = blockIdx.x>>6 (0 fwd, 1 bwd); 4 hidden units per block.
// Per-direction barrier domains (64 blocks each).
__global__ void __launch_bounds__(256, 1) lstm_ctx(
    const float* __restrict__ xwPF, const float* __restrict__ xwPB,
    const float* __restrict__ xwHF, const float* __restrict__ xwHB,
    const float* __restrict__ WhhF, const float* __restrict__ WhhB,
    float* __restrict__ hsPF, float* __restrict__ hsPB,
    float* __restrict__ hsHF, float* __restrict__ hsHB)
{
    int tid = threadIdx.x;
    int bt = tid >> 5, lane = tid & 31;
    int ul = lane & 3, kp = lane >> 2;
    int dir = blockIdx.x >> 6;
    int bd  = blockIdx.x & 63;
    int u   = bd * 4 + ul;
    const float* xwP = dir ? xwPB : xwPF;
    const float* xwH = dir ? xwHB : xwHF;
    const float* Whh = dir ? WhhB : WhhF;
    float* hsP = dir ? hsPB : hsPF;
    float* hsH = dir ? hsHB : hsHF;
    int b = bt*8 + kp;

    ull w[4][8][2];
#pragma unroll
    for (int g = 0; g < 4; g++)
#pragma unroll
        for (int j = 0; j < 8; j++)
            ldg_u64x2(Whh + (size_t)(g*HH + u) * HH + (kp + j*8) * 4, w[g][j][0], w[g][j][1]);

    float cP = 0.f, cH = 0.f;
    unsigned lgen = g_genA[dir];
    __syncthreads();

    for (int s = 0; s < STT; s++) {
        int ttP = dir ? (STT - 1 - s) : s;
        // prefetch x-projections (independent of h): hide DRAM latency behind barrier
        float xvP[4];
#pragma unroll
        for (int g = 0; g < 4; g++)
            xvP[g] = __ldg(xwP + ((size_t)b * STT + ttP) * G4 + g*HH + u);
        int ttH = dir ? (SLL - 1 - s) : s;
        float xvH[4];
        if (s < SLL) {
#pragma unroll
            for (int g = 0; g < 4; g++)
                xvH[g] = __ldg(xwH + ((size_t)b * SLL + ttH) * G4 + g*HH + u);
        }

        unsigned zoff = 0;
        if (s > 0) {
            grid_barrier(dir, 64u, lgen);
            zoff = opaque_zero(lgen);   // opaque 0: pins h loads after the barrier
        }

        float preP[4] = {0.f, 0.f, 0.f, 0.f};
        if (s > 0) {
            int tp = dir ? (ttP + 1) : (ttP - 1);
            gate_mma(hsP + (size_t)tp * HH + zoff, (size_t)STT * HH, w, bt, kp, preP);
        }
        float hP = lstm_cell(preP, xvP, cP);
        hsP[((size_t)b * STT + ttP) * HH + u] = hP;

        if (s < SLL) {
            float preH[4] = {0.f, 0.f, 0.f, 0.f};
            if (s > 0) {
                int tp = dir ? (ttH + 1) : (ttH - 1);
                gate_mma(hsH + (size_t)tp * HH + zoff, (size_t)SLL * HH, w, bt, kp, preH);
            }
            float hH = lstm_cell(preH, xvH, cH);
            hsH[((size_t)b * SLL + ttH) * HH + u] = hH;
        }
    }
}

// ---------------- aggregation BiLSTM: premise + hypothesis fused, finals only ----------
__global__ void __launch_bounds__(256, 1) lstm_agg(
    const float* __restrict__ mvP, const float* __restrict__ mvH,
    const float* __restrict__ WihF, const float* __restrict__ WihB,
    const float* __restrict__ bihF, const float* __restrict__ bhhF,
    const float* __restrict__ bihB, const float* __restrict__ bhhB,
    const float* __restrict__ WhhF, const float* __restrict__ WhhB,
    float* __restrict__ hping, float* __restrict__ fin)
{
    int tid = threadIdx.x;
    int bt = tid >> 5, lane = tid & 31;
    int ul = lane & 3, kp = lane >> 2;
    int dir = blockIdx.x >> 6;
    int bd  = blockIdx.x & 63;
    int u   = bd * 4 + ul;
    const float* Wih = dir ? WihB : WihF;
    const float* Whh = dir ? WhhB : WhhF;
    const float* bih = dir ? bihB : bihF;
    const float* bhh = dir ? bhhB : bhhF;
    float* finP = fin + (size_t)(0*2 + dir) * (BB*HH);
    float* finH = fin + (size_t)(1*2 + dir) * (BB*HH);
    float* bufP0 = hping + (size_t)((0*2 + dir)*2 + 0) * (BB*HH);
    float* bufP1 = hping + (size_t)((0*2 + dir)*2 + 1) * (BB*HH);
    float* bufH0 = hping + (size_t)((1*2 + dir)*2 + 0) * (BB*HH);
    float* bufH1 = hping + (size_t)((1*2 + dir)*2 + 1) * (BB*HH);
    int b = bt*8 + kp;

    ull w[4][8][2];
    float wih0[4], wih1[4], bias[4];
#pragma unroll
    for (int g = 0; g < 4; g++) {
        int r = g*HH + u;
#pragma unroll
        for (int j = 0; j < 8; j++)
            ldg_u64x2(Whh + (size_t)r * HH + (kp + j*8) * 4, w[g][j][0], w[g][j][1]);
        wih0[g] = __ldg(Wih + r*2);
        wih1[g] = __ldg(Wih + r*2 + 1);
        bias[g] = __ldg(bih + r) + __ldg(bhh + r);
    }

    float cP = 0.f, cH = 0.f;
    unsigned lgen = g_genA[dir];
    __syncthreads();

    for (int s = 0; s < STT; s++) {
        int ttP = dir ? (STT - 1 - s) : s;
        float2 mvvP = __ldg((const float2*)(mvP + ((size_t)b * STT + ttP) * 2));
        float xvP[4];
#pragma unroll
        for (int g = 0; g < 4; g++)
            xvP[g] = mvvP.x * wih0[g] + mvvP.y * wih1[g] + bias[g];
        int ttH = dir ? (SLL - 1 - s) : s;
        float xvH[4];
        if (s < SLL) {
            float2 mvvH = __ldg((const float2*)(mvH + ((size_t)b * SLL + ttH) * 2));
#pragma unroll
            for (int g = 0; g < 4; g++)
                xvH[g] = mvvH.x * wih0[g] + mvvH.y * wih1[g] + bias[g];
        }

        unsigned zoff = 0;
        if (s > 0) {
            grid_barrier(dir, 64u, lgen);
            zoff = opaque_zero(lgen);
        }

        {
            float* cur        = (s & 1) ? bufP1 : bufP0;
            const float* prev = (s & 1) ? bufP0 : bufP1;
            float pre[4] = {0.f, 0.f, 0.f, 0.f};
            if (s > 0) gate_mma(prev + zoff, (size_t)HH, w, bt, kp, pre);
            float h = lstm_cell(pre, xvP, cP);
            cur[(size_t)b * HH + u] = h;
            if (s == STT - 1) finP[(size_t)b * HH + u] = h;
        }
        if (s < SLL) {
            float* cur        = (s & 1) ? bufH1 : bufH0;
            const float* prev = (s & 1) ? bufH0 : bufH1;
            float pre[4] = {0.f, 0.f, 0.f, 0.f};
            if (s > 0) gate_mma(prev + zoff, (size_t)HH, w, bt, kp, pre);
            float h = lstm_cell(pre, xvH, cH);
            cur[(size_t)b * HH + u] = h;
            if (s == SLL - 1) finH[(size_t)b * HH + u] = h;
        }
    }
}

// ---------------- multi-perspective cosine matching (both sequences, one launch) --------
__global__ void __launch_bounds__(256) match_kernel(
    const float* __restrict__ cpf, const float* __restrict__ cpb,
    const float* __restrict__ chf, const float* __restrict__ chb,
    const float* __restrict__ w1, const float* __restrict__ w2,
    float* __restrict__ mvp, float* __restrict__ mvh)
{
    int warp = (blockIdx.x * blockDim.x + threadIdx.x) >> 5;
    int lane = threadIdx.x & 31;
    const float *x1, *y1v, *x2, *y2v;
    float* mv;
    int S;
    int b, s;
    if (warp < BB * STT) {
        b = warp / STT; s = warp % STT; S = STT;
        x1  = cpf + ((size_t)b * STT + s) * HH;
        y1v = chf + ((size_t)b * SLL + (SLL - 1)) * HH;
        x2  = cpb + ((size_t)b * STT + s) * HH;
        y2v = chb + ((size_t)b * SLL) * HH;
        mv  = mvp;
    } else {
        int wq = warp - BB * STT;
        b = wq / SLL; s = wq % SLL; S = SLL;
        x1  = chf + ((size_t)b * SLL + s) * HH;
        y1v = cpf + ((size_t)b * STT + (STT - 1)) * HH;
        x2  = chb + ((size_t)b * SLL + s) * HH;
        y2v = cpb + ((size_t)b * STT) * HH;
        mv  = mvh;
    }
    float n1 = 0.f, dx1 = 0.f, dy1 = 0.f, n2 = 0.f, dx2 = 0.f, dy2 = 0.f;
    for (int k = lane; k < HH; k += 32) {
        float wv = __ldg(w1 + k); float ww = wv * wv;
        float xv = __ldg(x1 + k), yv = __ldg(y1v + k);
        n1 += ww * xv * yv; dx1 += ww * xv * xv; dy1 += ww * yv * yv;
        float wv2 = __ldg(w2 + k); float ww2 = wv2 * wv2;
        float xv2 = __ldg(x2 + k), yv2 = __ldg(y2v + k);
        n2 += ww2 * xv2 * yv2; dx2 += ww2 * xv2 * xv2; dy2 += ww2 * yv2 * yv2;
    }
#pragma unroll
    for (int o = 16; o; o >>= 1) {
        n1 += __shfl_xor_sync(0xffffffffu, n1, o);
        dx1 += __shfl_xor_sync(0xffffffffu, dx1, o);
        dy1 += __shfl_xor_sync(0xffffffffu, dy1, o);
        n2 += __shfl_xor_sync(0xffffffffu, n2, o);
        dx2 += __shfl_xor_sync(0xffffffffu, dx2, o);
        dy2 += __shfl_xor_sync(0xffffffffu, dy2, o);
    }
    if (lane == 0) {
        mv[((size_t)b * S + s) * 2]     = n1 / fmaxf(sqrtf(dx1) * sqrtf(dy1), EPSV);
        mv[((size_t)b * S + s) * 2 + 1] = n2 / fmaxf(sqrtf(dx2) * sqrtf(dy2), EPSV);
    }
}

// ---------------- final MLP ----------------
__global__ void __launch_bounds__(256) final_fc(
    const float* __restrict__ fin,
    const float* __restrict__ W1, const float* __restrict__ b1,
    const float* __restrict__ W2, const float* __restrict__ b2,
    float* __restrict__ out)
{
    __shared__ float xs[1024];
    __shared__ float y1[512];
    int b = blockIdx.x, t = threadIdx.x;
    // fin segments: [pT_f][pT_b][hT_f][hT_b], each BB*HH
    xs[t]       = __ldg(fin + (size_t)(0*BB + b) * HH + t);
    xs[256 + t] = __ldg(fin + (size_t)(1*BB + b) * HH + t);
    xs[512 + t] = __ldg(fin + (size_t)(2*BB + b) * HH + t);
    xs[768 + t] = __ldg(fin + (size_t)(3*BB + b) * HH + t);
    __syncthreads();
    int w = t >> 5, lane = t & 31;
    for (int j0 = w * 4; j0 < 512; j0 += 32) {
#pragma unroll
        for (int jj = 0; jj < 4; jj++) {
            int jo = j0 + jj;
            const float4* wr = (const float4*)(W1 + (size_t)jo * 1024);
            float acc = 0.f;
            for (int i = lane; i < 256; i += 32) {
                float4 wv = __ldg(wr + i);
                float4 xv = *(const float4*)(xs + i*4);
                acc += wv.x*xv.x + wv.y*xv.y + wv.z*xv.z + wv.w*xv.w;
            }
#pragma unroll
            for (int o = 16; o; o >>= 1) acc += __shfl_xor_sync(0xffffffffu, acc, o);
            if (lane == 0) y1[jo] = tanhf(acc + __ldg(b1 + jo));
        }
    }
    __syncthreads();
    for (int jo = w; jo < NCL; jo += 8) {
        const float4* wr = (const float4*)(W2 + (size_t)jo * 512);
        float acc = 0.f;
        for (int i = lane; i < 128; i += 32) {
            float4 wv = __ldg(wr + i);
            float4 xv = *(const float4*)(y1 + i*4);
            acc += wv.x*xv.x + wv.y*xv.y + wv.z*xv.z + wv.w*xv.w;
        }
#pragma unroll
        for (int o = 16; o; o >>= 1) acc += __shfl_xor_sync(0xffffffffu, acc, o);
        if (lane == 0) out[(size_t)b*NCL + jo] = acc + __ldg(b2 + jo);
    }
}

// ---------------- host ----------------
extern "C" void kernel_launch(void* const* d_in, const int* in_sizes, int n_in,
                              void* d_out, int out_size)
{
    const int*   text  = (const int*)d_in[0];
    const int*   label = (const int*)d_in[1];
    const float* emb   = (const float*)d_in[2];
    const float* cWihF = (const float*)d_in[3];
    const float* cWhhF = (const float*)d_in[4];
    const float* cbihF = (const float*)d_in[5];
    const float* cbhhF = (const float*)d_in[6];
    const float* cWihB = (const float*)d_in[7];
    const float* cWhhB = (const float*)d_in[8];
    const float* cbihB = (const float*)d_in[9];
    const float* cbhhB = (const float*)d_in[10];
    const float* w1    = (const float*)d_in[11];
    const float* w2    = (const float*)d_in[12];
    const float* aWihF = (const float*)d_in[13];
    const float* aWhhF = (const float*)d_in[14];
    const float* abihF = (const float*)d_in[15];
    const float* abhhF = (const float*)d_in[16];
    const float* aWihB = (const float*)d_in[17];
    const float* aWhhB = (const float*)d_in[18];
    const float* abihB = (const float*)d_in[19];
    const float* abhhB = (const float*)d_in[20];
    const float* fc1W  = (const float*)d_in[21];
    const float* fc1b  = (const float*)d_in[22];
    const float* fc2W  = (const float*)d_in[23];
    const float* fc2b  = (const float*)d_in[24];
    float* out = (float*)d_out;

    void* p;
    cudaGetSymbolAddress(&p, g_xw_pf); float* xwpf = (float*)p;
    cudaGetSymbolAddress(&p, g_xw_pb); float* xwpb = (float*)p;
    cudaGetSymbolAddress(&p, g_xw_hf); float* xwhf = (float*)p;
    cudaGetSymbolAddress(&p, g_xw_hb); float* xwhb = (float*)p;
    cudaGetSymbolAddress(&p, g_cpf);   float* cpf  = (float*)p;
    cudaGetSymbolAddress(&p, g_cpb);   float* cpb  = (float*)p;
    cudaGetSymbolAddress(&p, g_chf);   float* chf  = (float*)p;
    cudaGetSymbolAddress(&p, g_chb);   float* chb  = (float*)p;
    cudaGetSymbolAddress(&p, g_mvp);   float* mvp  = (float*)p;
    cudaGetSymbolAddress(&p, g_mvh);   float* mvh  = (float*)p;
    cudaGetSymbolAddress(&p, g_hping); float* hping = (float*)p;
    cudaGetSymbolAddress(&p, g_fin);   float* fin  = (float*)p;

    // Force 1 CTA/SM on the persistent kernels: all 128 blocks co-resident, one SM each.
    const int DUMMY_SMEM = 120 * 1024;
    cudaFuncSetAttribute(lstm_ctx, cudaFuncAttributeMaxDynamicSharedMemorySize, DUMMY_SMEM);
    cudaFuncSetAttribute(lstm_agg, cudaFuncAttributeMaxDynamicSharedMemorySize, DUMMY_SMEM);

    // 1) xW precompute for both sequences and both directions (one launch)
    gemm2<<<dim3(64, 2), 256>>>(text, label, emb, cWihF, cWihB,
                                cbihF, cbhhF, cbihB, cbhhB,
                                xwpf, xwpb, xwhf, xwhb);

    // 2) context BiLSTM recurrence, premise + hypothesis fused (persistent)
    lstm_ctx<<<NBLK, 256, DUMMY_SMEM>>>(xwpf, xwpb, xwhf, xwhb,
                                        cWhhF, cWhhB, cpf, cpb, chf, chb);

    // 3) multi-perspective matching (both sequences)
    match_kernel<<<(BB*STT + BB*SLL)/8, 256>>>(cpf, cpb, chf, chb, w1, w2, mvp, mvh);

    // 4) aggregation BiLSTM, premise + hypothesis fused (persistent, finals only)
    lstm_agg<<<NBLK, 256, DUMMY_SMEM>>>(mvp, mvh, aWihF, aWihB,
                                        abihF, abhhF, abihB, abhhB,
                                        aWhhF, aWhhB, hping, fin);

    // 5) final MLP
    final_fc<<<BB, 256>>>(fin, fc1W, fc1b, fc2W, fc2b, out);
}